// round 15
// baseline (speedup 1.0000x reference)
#include <cuda_runtime.h>
#include <cuda_bf16.h>
#include <cuda_fp16.h>
#include <cstdint>

// Problem constants
#define TT   500
#define BB   128
#define CC   700
#define CP   704      // padded K
#define HH   1024
#define OO   20
#define MM   (TT*BB)  // 64000

// ---------------------------------------------------------------------------
// Device scratch
__device__ __nv_bfloat16 g_xh[(size_t)MM * CP];   // delayed input hi
__device__ __nv_bfloat16 g_xl[(size_t)MM * CP];   // delayed input lo
__device__ __nv_bfloat16 g_wh[(size_t)HH * CP];   // w_in hi  [h][k]
__device__ __nv_bfloat16 g_wl[(size_t)HH * CP];   // w_in lo
__device__ __half g_wrecH[(size_t)HH * HH];       // w_rec transposed [j][h], fp16
__device__ float g_woutT[(size_t)HH * OO];        // w_out transposed [j][o]
__device__ float g_Iin[(size_t)MM * HH];          // I_in[m][h]
__device__ int   g_done[TT];                      // per-timestep tile counters

// ---------------------------------------------------------------------------
__device__ __forceinline__ uint32_t smem_u32(const void* p) {
    uint32_t a;
    asm("{ .reg .u64 t; cvta.to.shared.u64 t, %1; cvt.u32.u64 %0, t; }" : "=r"(a) : "l"(p));
    return a;
}
#define CP16(dst, src) asm volatile("cp.async.cg.shared.global [%0], [%1], 16;" :: "r"(dst), "l"(src) : "memory")
#define CP_COMMIT()    asm volatile("cp.async.commit_group;" ::: "memory")
#define CP_WAIT1()     asm volatile("cp.async.wait_group 1;" ::: "memory")

__device__ __forceinline__ void ldsm_x4(uint32_t* r, uint32_t addr) {
    asm volatile("ldmatrix.sync.aligned.m8n8.x4.shared.b16 {%0,%1,%2,%3}, [%4];"
        : "=r"(r[0]), "=r"(r[1]), "=r"(r[2]), "=r"(r[3]) : "r"(addr));
}
__device__ __forceinline__ void mma16816(float* d, const uint32_t* a, uint32_t b0, uint32_t b1) {
    asm volatile(
        "mma.sync.aligned.m16n8k16.row.col.f32.bf16.bf16.f32 "
        "{%0,%1,%2,%3}, {%4,%5,%6,%7}, {%8,%9}, {%0,%1,%2,%3};"
        : "+f"(d[0]), "+f"(d[1]), "+f"(d[2]), "+f"(d[3])
        : "r"(a[0]), "r"(a[1]), "r"(a[2]), "r"(a[3]), "r"(b0), "r"(b1));
}

// ---------------------------------------------------------------------------
// Prep: split w_in into bf16 hi/lo, [h][kp], zero pad k>=700
__global__ void prep_w(const float* __restrict__ w_in) {
    int idx = blockIdx.x * blockDim.x + threadIdx.x;
    if (idx >= HH * CP) return;
    int h = idx / CP;
    int k = idx - h * CP;
    float v = (k < CC) ? w_in[h * CC + k] : 0.f;
    __nv_bfloat16 hi = __float2bfloat16(v);
    g_wh[idx] = hi;
    g_wl[idx] = __float2bfloat16(v - __bfloat162float(hi));
}

// Prep: transpose w_rec -> fp16 [j][h]; transpose w_out -> [j][o]; zero flags
__global__ void prep_wrec_wout(const float* __restrict__ w_rec,
                               const float* __restrict__ w_out) {
    int idx = blockIdx.x * blockDim.x + threadIdx.x;
    if (idx < HH * HH) {
        int j = idx >> 10;
        int h = idx & 1023;
        g_wrecH[idx] = __float2half(w_rec[h * HH + j]);
    }
    if (idx < HH * OO) {
        int j = idx / OO;
        int o = idx - j * OO;
        g_woutT[idx] = w_out[o * HH + j];
    }
    if (idx < TT) g_done[idx] = 0;
}

// ---------------------------------------------------------------------------
// build_xd tiled: XT=64 (47KB smem -> 4 CTAs/SM), 2 cols per thread (float2).
#define XT 64
#define XC 128
#define XROWS (XT + 30)     // 94
#define XD_SMEM (XROWS * XC * 4)   // 48128 B

__global__ __launch_bounds__(256) void build_xd(const float* __restrict__ x,
                                                const int* __restrict__ delays) {
    extern __shared__ float sx[];
    __shared__ int sd[XC];

    const int c0 = blockIdx.x * XC;
    const int t0 = blockIdx.y * XT;
    const int b  = blockIdx.z;
    const int tid = threadIdx.x;

    if (tid < XC) {
        int c = c0 + tid;
        sd[tid] = (c < CC) ? delays[c] : 0;
    }

    const float* xb = x + (size_t)b * TT * CC;
    #pragma unroll
    for (int it = 0; it < 24; ++it) {
        int idx = it * 256 + tid;
        if (idx >= XROWS * (XC / 2)) break;
        int row = idx >> 6;
        int col = (idx & 63) * 2;
        int g = t0 - 30 + row;
        int c = c0 + col;
        float2 v = make_float2(0.f, 0.f);
        if (g >= 0 && g < TT && c < CC)
            v = *(const float2*)&xb[(size_t)g * CC + c];
        *(float2*)&sx[row * XC + col] = v;
    }
    __syncthreads();

    #pragma unroll
    for (int it = 0; it < 16; ++it) {
        int idx = it * 256 + tid;
        int tt = idx >> 6;
        int col = (idx & 63) * 2;
        int t = t0 + tt;
        if (t >= TT || c0 + col >= CP) continue;
        float v0 = sx[(tt + 30 - sd[col]) * XC + col];
        float v1 = sx[(tt + 30 - sd[col + 1]) * XC + col + 1];
        __nv_bfloat16 h0 = __float2bfloat16(v0);
        __nv_bfloat16 h1 = __float2bfloat16(v1);
        __nv_bfloat16 l0 = __float2bfloat16(v0 - __bfloat162float(h0));
        __nv_bfloat16 l1 = __float2bfloat16(v1 - __bfloat162float(h1));
        size_t o = (size_t)(t * BB + b) * CP + c0 + col;
        __nv_bfloat162 hh; hh.x = h0; hh.y = h1;
        __nv_bfloat162 ll; ll.x = l0; ll.y = l1;
        *(__nv_bfloat162*)&g_xh[o] = hh;
        *(__nv_bfloat162*)&g_xl[o] = ll;
    }
}

// ---------------------------------------------------------------------------
// Fused kernel: bids 0..127 = SNN consumers (1 batch each),
// bids 128..295 = PERSISTENT GEMM producers, each looping tiles tau = pid+k*168
// with a continuous cross-tile cp.async double-buffer stream.
#define T_STRIDE 80
#define TILE_BYTES 10240
#define BUF_BYTES  40960
#define FUSED_SMEM 81920
#define NCHUNK 22          // 704/32
#define NGTILE_N 8
#define NSNN 128
#define NPROD 168
#define NTILES 4000        // 500 t * 8 n

__device__ __forceinline__ void gemm_body(char* smem, int pid) {
    const uint32_t sb = smem_u32(smem);
    const int tid = threadIdx.x;
    const int lane = tid & 31;
    const int wid = tid >> 5;
    const int wm = wid & 3;
    const int wn = wid >> 2;

    // ---- load cursor (runs 2 chunks ahead, across tile boundaries) ----
    int tau_l = pid;          // tile being loaded
    int kc_l  = 0;            // chunk within tau_l
    auto issue_chunk = [&]() {
        if (tau_l < NTILES) {
            const int Mb = (tau_l >> 3) * 128;
            const int Nb = (tau_l & 7) * 128;
            const int k0 = kc_l * 32;
            const int buf = kc_l & 1;          // NCHUNK even -> parity continuous
            #pragma unroll
            for (int j = 0; j < 2; ++j) {
                int i = tid + 256 * j;
                int r = i >> 2, c = i & 3;
                uint32_t doff = (uint32_t)(r * T_STRIDE + c * 16);
                size_t aoff = (size_t)(Mb + r) * CP + k0 + c * 8;
                size_t boff = (size_t)(Nb + r) * CP + k0 + c * 8;
                uint32_t base = sb + buf * BUF_BYTES + doff;
                CP16(base,                  g_xh + aoff);
                CP16(base + TILE_BYTES,     g_xl + aoff);
                CP16(base + 2 * TILE_BYTES, g_wh + boff);
                CP16(base + 3 * TILE_BYTES, g_wl + boff);
            }
            if (++kc_l == NCHUNK) { kc_l = 0; tau_l += NPROD; }
        }
        CP_COMMIT();          // unconditional: empty groups keep wait counts exact
    };

    issue_chunk();            // (pid, 0)
    issue_chunk();            // (pid, 1)

    const uint32_t a_row = (uint32_t)(wm * 32 + (lane & 15));
    const uint32_t a_kb  = (uint32_t)((lane >> 4) * 16);
    const uint32_t b_row = (uint32_t)(wn * 64 + (lane & 7) + ((lane & 16) ? 8 : 0));
    const uint32_t b_kb  = (uint32_t)(((lane >> 3) & 1) * 16);

    for (int tau = pid; tau < NTILES; tau += NPROD) {
        const int by = tau >> 3;
        const int Mb = by * 128;
        const int Nb = (tau & 7) * 128;

        float d[2][8][4];
        #pragma unroll
        for (int i = 0; i < 2; i++)
            #pragma unroll
            for (int j = 0; j < 8; j++)
                #pragma unroll
                for (int q = 0; q < 4; q++) d[i][j][q] = 0.f;

        for (int kc = 0; kc < NCHUNK; ++kc) {
            const int buf = kc & 1;
            CP_WAIT1();               // chunk kc of this tile complete
            __syncthreads();
            const uint32_t Ah = sb + buf * BUF_BYTES;
            const uint32_t Al = Ah + TILE_BYTES;
            const uint32_t Bh = Ah + 2 * TILE_BYTES;
            const uint32_t Bl = Ah + 3 * TILE_BYTES;

            #pragma unroll
            for (int kk = 0; kk < 2; ++kk) {
                const uint32_t kbase = (uint32_t)(kk * 32);
                uint32_t ah[2][4], al[2][4];
                #pragma unroll
                for (int mf = 0; mf < 2; ++mf) {
                    uint32_t ao = (a_row + mf * 16) * T_STRIDE + kbase + a_kb;
                    ldsm_x4(ah[mf], Ah + ao);
                    ldsm_x4(al[mf], Al + ao);
                }
                uint32_t bh[4][4], bl[4][4];
                #pragma unroll
                for (int nb = 0; nb < 4; ++nb) {
                    uint32_t bo = (b_row + nb * 16) * T_STRIDE + kbase + b_kb;
                    ldsm_x4(bh[nb], Bh + bo);
                    ldsm_x4(bl[nb], Bl + bo);
                }
                #pragma unroll
                for (int mf = 0; mf < 2; ++mf)
                    #pragma unroll
                    for (int nf = 0; nf < 8; ++nf) {
                        const int nb = nf >> 1, s = (nf & 1) * 2;
                        mma16816(d[mf][nf], ah[mf], bh[nb][s], bh[nb][s + 1]);
                        mma16816(d[mf][nf], ah[mf], bl[nb][s], bl[nb][s + 1]);
                        mma16816(d[mf][nf], al[mf], bh[nb][s], bh[nb][s + 1]);
                    }
            }
            __syncthreads();          // all reads of buf done
            issue_chunk();            // overwrites buf with chunk kc+2 of stream
        }

        // Epilogue (overlaps next tile's in-flight loads)
        #pragma unroll
        for (int mf = 0; mf < 2; ++mf) {
            const int row = Mb + wm * 32 + mf * 16 + (lane >> 2);
            #pragma unroll
            for (int nf = 0; nf < 8; ++nf) {
                const int col = Nb + wn * 64 + nf * 8 + (lane & 3) * 2;
                float2* p0 = (float2*)&g_Iin[(size_t)row * HH + col];
                float2* p1 = (float2*)&g_Iin[(size_t)(row + 8) * HH + col];
                *p0 = make_float2(d[mf][nf][0], d[mf][nf][1]);
                *p1 = make_float2(d[mf][nf][2], d[mf][nf][3]);
            }
        }
        __threadfence();
        __syncthreads();
        if (tid == 0) atomicAdd(&g_done[by], 1);
    }
}

// SNN consumer: 1 batch per CTA, consecutive unit mapping h = 4*tid..4*tid+3.
__device__ __forceinline__ void snn_body(
    char* smem,
    const float* __restrict__ alpha, const float* __restrict__ rho,
    const float* __restrict__ beta_a, const float* __restrict__ beta_out,
    float* __restrict__ out)
{
    const int b = blockIdx.x;
    const int tid = threadIdx.x;
    const int lane = tid & 31;
    const int wid = tid >> 5;

    int* act  = (int*)smem;             // [HH]
    int* wsum = act + HH;               // [8]

    float4 al4 = *(const float4*)&alpha[4 * tid];
    float4 rh4 = *(const float4*)&rho[4 * tid];
    float4 ba4 = *(const float4*)&beta_a[4 * tid];
    float al[4] = {al4.x, al4.y, al4.z, al4.w};
    float rh[4] = {rh4.x, rh4.y, rh4.z, rh4.w};
    float ba[4] = {ba4.x, ba4.y, ba4.z, ba4.w};

    float v[4] = {0.f, 0.f, 0.f, 0.f};
    float aa[4] = {0.f, 0.f, 0.f, 0.f};
    float spk[4] = {0.f, 0.f, 0.f, 0.f};
    float v_out = 0.f, osum = 0.f, bo = 0.f;
    if (tid < OO) bo = beta_out[tid];
    int n_act = 0;

    const __half* __restrict__ wr = g_wrecH;

    for (int t = 0; t < TT; ++t) {
        if (tid == 0) {
            int dv;
            do {
                asm volatile("ld.acquire.gpu.global.b32 %0, [%1];"
                             : "=r"(dv) : "l"(&g_done[t]) : "memory");
                if (dv < NGTILE_N) __nanosleep(200);
            } while (dv < NGTILE_N);
        }
        __syncthreads();

        float4 Ic = *(const float4*)&g_Iin[(size_t)(t * BB + b) * HH + 4 * tid];
        float Icur[4] = {Ic.x, Ic.y, Ic.z, Ic.w};

        float Irec[4] = {0.f, 0.f, 0.f, 0.f};
        for (int i = 0; i < n_act; ++i) {
            uint2 w2 = *(const uint2*)(wr + (size_t)act[i] * HH + 4 * tid);
            __half2 p0 = *reinterpret_cast<__half2*>(&w2.x);
            __half2 p1 = *reinterpret_cast<__half2*>(&w2.y);
            Irec[0] += __low2float(p0);
            Irec[1] += __high2float(p0);
            Irec[2] += __low2float(p1);
            Irec[3] += __high2float(p1);
        }

        float spkn[4];
        #pragma unroll
        for (int k = 0; k < 4; ++k) {
            float I1 = Icur[k] + Irec[k];
            float vn = al[k] * v[k] * (1.f - spk[k]) + (1.f - al[k]) * (I1 - aa[k]);
            spkn[k] = (vn > 1.0f) ? 1.f : 0.f;
            aa[k] = rh[k] * aa[k] + (1.f - rh[k]) * (ba[k] * vn + spkn[k]);
            v[k] = vn;
            spk[k] = spkn[k];
        }

        unsigned mybits = (spkn[0] != 0.f ? 1u : 0u) | (spkn[1] != 0.f ? 2u : 0u)
                        | (spkn[2] != 0.f ? 4u : 0u) | (spkn[3] != 0.f ? 8u : 0u);
        int c = __popc(mybits);
        int incl = c;
        #pragma unroll
        for (int dd = 1; dd < 32; dd <<= 1) {
            int y = __shfl_up_sync(0xffffffffu, incl, dd);
            if (lane >= dd) incl += y;
        }
        if (lane == 31) wsum[wid] = incl;
        __syncthreads();
        {
            int woffv = 0, tot = 0;
            #pragma unroll
            for (int w = 0; w < 8; ++w) {
                int s = wsum[w];
                if (w < wid) woffv += s;
                tot += s;
            }
            n_act = tot;
            int p = woffv + incl - c;
            int h0 = 4 * tid;
            if (mybits & 1u) act[p++] = h0;
            if (mybits & 2u) act[p++] = h0 + 1;
            if (mybits & 4u) act[p++] = h0 + 2;
            if (mybits & 8u) act[p++] = h0 + 3;
        }
        __syncthreads();

        if (tid < OO) {
            float accum = 0.f;
            for (int i = 0; i < n_act; ++i)
                accum += g_woutT[(size_t)act[i] * OO + tid];
            v_out = bo * v_out + (1.f - bo) * accum;
            osum += v_out;
        }
    }

    if (tid < OO) out[b * OO + tid] = osum * (1.f / (float)TT);
}

__global__ __launch_bounds__(256, 2) void fused(
    const float* __restrict__ alpha, const float* __restrict__ rho,
    const float* __restrict__ beta_a, const float* __restrict__ beta_out,
    float* __restrict__ out)
{
    extern __shared__ char smem[];
    if (blockIdx.x < NSNN)
        snn_body(smem, alpha, rho, beta_a, beta_out, out);
    else
        gemm_body(smem, blockIdx.x - NSNN);
}

// ---------------------------------------------------------------------------
extern "C" void kernel_launch(void* const* d_in, const int* in_sizes, int n_in,
                              void* d_out, int out_size)
{
    const float* x        = (const float*)d_in[0];
    const int*   delays   = (const int*)  d_in[1];
    const float* w_in     = (const float*)d_in[2];
    const float* w_rec    = (const float*)d_in[3];
    const float* w_out    = (const float*)d_in[4];
    const float* alpha    = (const float*)d_in[5];
    const float* rho      = (const float*)d_in[6];
    const float* beta_a   = (const float*)d_in[7];
    const float* beta_out = (const float*)d_in[8];
    float* out = (float*)d_out;

    static bool attr_set = false;
    if (!attr_set) {
        cudaFuncSetAttribute(fused, cudaFuncAttributeMaxDynamicSharedMemorySize, FUSED_SMEM);
        cudaFuncSetAttribute(build_xd, cudaFuncAttributeMaxDynamicSharedMemorySize, XD_SMEM);
        attr_set = true;
    }

    prep_w        <<<(HH * CP + 255) / 256, 256>>>(w_in);
    prep_wrec_wout<<<(HH * HH + 255) / 256, 256>>>(w_rec, w_out);
    {
        dim3 grid((CP + XC - 1) / XC, (TT + XT - 1) / XT, BB);  // (6,8,128)
        build_xd<<<grid, 256, XD_SMEM>>>(x, delays);
    }
    fused<<<NSNN + NPROD, 256, FUSED_SMEM>>>(alpha, rho, beta_a, beta_out, out);
}

// round 16
// speedup vs baseline: 1.1844x; 1.1844x over previous
#include <cuda_runtime.h>
#include <cuda_bf16.h>
#include <cuda_fp16.h>
#include <cstdint>

// Problem constants
#define TT   500
#define BB   128
#define CC   700
#define CP   704      // padded K
#define HH   1024
#define OO   20
#define MM   (TT*BB)  // 64000

// ---------------------------------------------------------------------------
// Device scratch
__device__ __nv_bfloat16 g_xh[(size_t)MM * CP];   // delayed input hi
__device__ __nv_bfloat16 g_xl[(size_t)MM * CP];   // delayed input lo
__device__ __nv_bfloat16 g_wh[(size_t)HH * CP];   // w_in hi  [h][k]
__device__ __nv_bfloat16 g_wl[(size_t)HH * CP];   // w_in lo
__device__ __half g_wrecH[(size_t)HH * HH];       // w_rec transposed [j][h], fp16
__device__ float g_woutT[(size_t)HH * OO];        // w_out transposed [j][o]
__device__ float g_Iin[(size_t)MM * HH];          // I_in[m][h]
__device__ int   g_done[TT];                      // per-timestep tile counters
__device__ int   g_xd_ready[8];                   // per-64-t-tile build counters
__device__ int   g_w_ready;                       // prep_w completion counter
__device__ int   g_wr_ready;                      // prep_wrec completion counter

// Grid layout (bid order = dispatch order; prefix CTAs never spin)
#define NPW   128                   // [0, 128)      prep_w
#define NPR   128                   // [128, 256)    prep_wrec/wout
#define NBLD  1024                  // [256, 1280)   build_xd (tt = q>>7, b = q&127)
#define NSNN  128                   // [1280, 1408)  SNN consumers
#define NGEMM 4000                  // [1408, 5408)  GEMM producers
#define GRID_TOTAL (NPW + NPR + NBLD + NSNN + NGEMM)

// ---------------------------------------------------------------------------
__device__ __forceinline__ uint32_t smem_u32(const void* p) {
    uint32_t a;
    asm("{ .reg .u64 t; cvta.to.shared.u64 t, %1; cvt.u32.u64 %0, t; }" : "=r"(a) : "l"(p));
    return a;
}
__device__ __forceinline__ int ld_acq(const int* p) {
    int v;
    asm volatile("ld.acquire.gpu.global.b32 %0, [%1];" : "=r"(v) : "l"(p) : "memory");
    return v;
}
#define SPIN_UNTIL(addr, target) do { \
    int _v; \
    do { _v = ld_acq(addr); if (_v < (target)) __nanosleep(200); } while (_v < (target)); \
} while (0)

#define CP16(dst, src) asm volatile("cp.async.cg.shared.global [%0], [%1], 16;" :: "r"(dst), "l"(src) : "memory")
#define CP_COMMIT()    asm volatile("cp.async.commit_group;" ::: "memory")
#define CP_WAIT1()     asm volatile("cp.async.wait_group 1;" ::: "memory")

__device__ __forceinline__ void ldsm_x4(uint32_t* r, uint32_t addr) {
    asm volatile("ldmatrix.sync.aligned.m8n8.x4.shared.b16 {%0,%1,%2,%3}, [%4];"
        : "=r"(r[0]), "=r"(r[1]), "=r"(r[2]), "=r"(r[3]) : "r"(addr));
}
__device__ __forceinline__ void mma16816(float* d, const uint32_t* a, uint32_t b0, uint32_t b1) {
    asm volatile(
        "mma.sync.aligned.m16n8k16.row.col.f32.bf16.bf16.f32 "
        "{%0,%1,%2,%3}, {%4,%5,%6,%7}, {%8,%9}, {%0,%1,%2,%3};"
        : "+f"(d[0]), "+f"(d[1]), "+f"(d[2]), "+f"(d[3])
        : "r"(a[0]), "r"(a[1]), "r"(a[2]), "r"(a[3]), "r"(b0), "r"(b1));
}

// ---------------------------------------------------------------------------
// Flag zeroing (per graph replay, before the mega kernel)
__global__ void zero_flags(void) {
    int i = threadIdx.x;
    if (i < TT) g_done[i] = 0;
    if (i + 512 < TT) g_done[i + 512] = 0;
    if (i < 8) g_xd_ready[i] = 0;
    if (i == 0) { g_w_ready = 0; g_wr_ready = 0; }
}

// ---------------------------------------------------------------------------
// Mega-kernel bodies
// ---------------------------------------------------------------------------
__device__ void prep_w_body(const float* __restrict__ w_in) {
    const int tid = threadIdx.x;
    for (int idx = blockIdx.x * 256 + tid; idx < HH * CP; idx += NPW * 256) {
        int h = idx / CP;
        int k = idx - h * CP;
        float v = (k < CC) ? w_in[h * CC + k] : 0.f;
        __nv_bfloat16 hi = __float2bfloat16(v);
        g_wh[idx] = hi;
        g_wl[idx] = __float2bfloat16(v - __bfloat162float(hi));
    }
    __threadfence();
    __syncthreads();
    if (tid == 0) atomicAdd(&g_w_ready, 1);
}

__device__ void prep_wrec_body(const float* __restrict__ w_rec,
                               const float* __restrict__ w_out, int q) {
    const int tid = threadIdx.x;
    for (int idx = q * 256 + tid; idx < HH * HH; idx += NPR * 256) {
        int j = idx >> 10;
        int h = idx & 1023;
        g_wrecH[idx] = __float2half(w_rec[h * HH + j]);
    }
    for (int idx = q * 256 + tid; idx < HH * OO; idx += NPR * 256) {
        int j = idx / OO;
        int o = idx - j * OO;
        g_woutT[idx] = w_out[o * HH + j];
    }
    __threadfence();
    __syncthreads();
    if (tid == 0) atomicAdd(&g_wr_ready, 1);
}

// build: one (64-t tile, batch) per CTA; loops 6 c-tiles of 128 channels.
__device__ void build_body(char* smem, const float* __restrict__ x,
                           const int* __restrict__ delays, int q) {
    float* sx = (float*)smem;           // [94][128] = 48128 B
    __shared__ int sd[128];
    const int tt = q >> 7;              // 0..7
    const int b  = q & 127;
    const int t0 = tt * 64;
    const int tid = threadIdx.x;
    const float* xb = x + (size_t)b * TT * CC;

    for (int c0 = 0; c0 < CP; c0 += 128) {
        __syncthreads();                // protect previous c-tile's reads
        if (tid < 128) {
            int c = c0 + tid;
            sd[tid] = (c < CC) ? delays[c] : 0;
        }
        #pragma unroll
        for (int it = 0; it < 24; ++it) {
            int idx = it * 256 + tid;
            if (idx >= 94 * 64) break;  // 94 rows x 64 float2
            int row = idx >> 6;
            int col = (idx & 63) * 2;
            int g = t0 - 30 + row;
            int c = c0 + col;
            float2 v = make_float2(0.f, 0.f);
            if (g >= 0 && g < TT && c < CC)
                v = *(const float2*)&xb[(size_t)g * CC + c];
            *(float2*)&sx[row * 128 + col] = v;
        }
        __syncthreads();
        #pragma unroll
        for (int it = 0; it < 16; ++it) {
            int idx = it * 256 + tid;   // 64 rows x 64 float2
            int ttr = idx >> 6;
            int col = (idx & 63) * 2;
            int t = t0 + ttr;
            if (t >= TT || c0 + col >= CP) continue;
            float v0 = sx[(ttr + 30 - sd[col]) * 128 + col];
            float v1 = sx[(ttr + 30 - sd[col + 1]) * 128 + col + 1];
            __nv_bfloat16 h0 = __float2bfloat16(v0);
            __nv_bfloat16 h1 = __float2bfloat16(v1);
            __nv_bfloat16 l0 = __float2bfloat16(v0 - __bfloat162float(h0));
            __nv_bfloat16 l1 = __float2bfloat16(v1 - __bfloat162float(h1));
            size_t o = (size_t)(t * BB + b) * CP + c0 + col;
            __nv_bfloat162 hh; hh.x = h0; hh.y = h1;
            __nv_bfloat162 ll; ll.x = l0; ll.y = l1;
            *(__nv_bfloat162*)&g_xh[o] = hh;
            *(__nv_bfloat162*)&g_xl[o] = ll;
        }
    }
    __threadfence();
    __syncthreads();
    if (tid == 0) atomicAdd(&g_xd_ready[tt], 1);
}

// ---------------------------------------------------------------------------
// GEMM producer (byte-identical math to R14; adds readiness spin at entry)
#define T_STRIDE 80
#define TILE_BYTES 10240
#define BUF_BYTES  40960
#define FUSED_SMEM 81920
#define NCHUNK 22          // 704/32
#define NGTILE_N 8

__device__ void gemm_body(char* smem, int gid) {
    const uint32_t sb = smem_u32(smem);
    const int tid = threadIdx.x;
    const int lane = tid & 31;
    const int wid = tid >> 5;
    const int wm = wid & 3;
    const int wn = wid >> 2;
    const int by = gid >> 3;       // timestep t
    const int Nb = (gid & 7) * 128;
    const int Mb = by * 128;
    const int tt = by >> 6;        // 64-t build tile

    // wait for weights + this tile's delayed-input block
    if (tid == 0) {
        SPIN_UNTIL(&g_w_ready, NPW);
        SPIN_UNTIL(&g_xd_ready[tt], 128);
    }
    __syncthreads();

    float d[2][8][4];
    #pragma unroll
    for (int i = 0; i < 2; i++)
        #pragma unroll
        for (int j = 0; j < 8; j++)
            #pragma unroll
            for (int q = 0; q < 4; q++) d[i][j][q] = 0.f;

    auto load_chunk = [&](int kc, int buf) {
        const int k0 = kc * 32;
        #pragma unroll
        for (int j = 0; j < 2; ++j) {
            int i = tid + 256 * j;
            int r = i >> 2, c = i & 3;
            uint32_t doff = (uint32_t)(r * T_STRIDE + c * 16);
            size_t aoff = (size_t)(Mb + r) * CP + k0 + c * 8;
            size_t boff = (size_t)(Nb + r) * CP + k0 + c * 8;
            uint32_t base = sb + buf * BUF_BYTES + doff;
            CP16(base,                  g_xh + aoff);
            CP16(base + TILE_BYTES,     g_xl + aoff);
            CP16(base + 2 * TILE_BYTES, g_wh + boff);
            CP16(base + 3 * TILE_BYTES, g_wl + boff);
        }
    };

    load_chunk(0, 0); CP_COMMIT();
    load_chunk(1, 1); CP_COMMIT();

    const uint32_t a_row = (uint32_t)(wm * 32 + (lane & 15));
    const uint32_t a_kb  = (uint32_t)((lane >> 4) * 16);
    const uint32_t b_row = (uint32_t)(wn * 64 + (lane & 7) + ((lane & 16) ? 8 : 0));
    const uint32_t b_kb  = (uint32_t)(((lane >> 3) & 1) * 16);

    for (int kc = 0; kc < NCHUNK; ++kc) {
        const int buf = kc & 1;
        CP_WAIT1();
        __syncthreads();
        const uint32_t Ah = sb + buf * BUF_BYTES;
        const uint32_t Al = Ah + TILE_BYTES;
        const uint32_t Bh = Ah + 2 * TILE_BYTES;
        const uint32_t Bl = Ah + 3 * TILE_BYTES;

        #pragma unroll
        for (int kk = 0; kk < 2; ++kk) {
            const uint32_t kbase = (uint32_t)(kk * 32);
            uint32_t ah[2][4], al[2][4];
            #pragma unroll
            for (int mf = 0; mf < 2; ++mf) {
                uint32_t ao = (a_row + mf * 16) * T_STRIDE + kbase + a_kb;
                ldsm_x4(ah[mf], Ah + ao);
                ldsm_x4(al[mf], Al + ao);
            }
            uint32_t bh[4][4], bl[4][4];
            #pragma unroll
            for (int nb = 0; nb < 4; ++nb) {
                uint32_t bo = (b_row + nb * 16) * T_STRIDE + kbase + b_kb;
                ldsm_x4(bh[nb], Bh + bo);
                ldsm_x4(bl[nb], Bl + bo);
            }
            #pragma unroll
            for (int mf = 0; mf < 2; ++mf)
                #pragma unroll
                for (int nf = 0; nf < 8; ++nf) {
                    const int nb = nf >> 1, s = (nf & 1) * 2;
                    mma16816(d[mf][nf], ah[mf], bh[nb][s], bh[nb][s + 1]);
                    mma16816(d[mf][nf], ah[mf], bl[nb][s], bl[nb][s + 1]);
                    mma16816(d[mf][nf], al[mf], bh[nb][s], bh[nb][s + 1]);
                }
        }
        __syncthreads();
        if (kc + 2 < NCHUNK) load_chunk(kc + 2, buf);
        CP_COMMIT();
    }

    #pragma unroll
    for (int mf = 0; mf < 2; ++mf) {
        const int row = Mb + wm * 32 + mf * 16 + (lane >> 2);
        #pragma unroll
        for (int nf = 0; nf < 8; ++nf) {
            const int col = Nb + wn * 64 + nf * 8 + (lane & 3) * 2;
            float2* p0 = (float2*)&g_Iin[(size_t)row * HH + col];
            float2* p1 = (float2*)&g_Iin[(size_t)(row + 8) * HH + col];
            *p0 = make_float2(d[mf][nf][0], d[mf][nf][1]);
            *p1 = make_float2(d[mf][nf][2], d[mf][nf][3]);
        }
    }

    __threadfence();
    __syncthreads();
    if (tid == 0) atomicAdd(&g_done[by], 1);
}

// ---------------------------------------------------------------------------
// SNN consumer: 1 batch per CTA, consecutive unit mapping (proven bit-exact)
__device__ void snn_body(
    char* smem, int b,
    const float* __restrict__ alpha, const float* __restrict__ rho,
    const float* __restrict__ beta_a, const float* __restrict__ beta_out,
    float* __restrict__ out)
{
    const int tid = threadIdx.x;
    const int lane = tid & 31;
    const int wid = tid >> 5;

    int* act  = (int*)smem;             // [HH]
    int* wsum = act + HH;               // [8]

    // wrec/wout must be ready before first gather (t>=1); wait once up front
    if (tid == 0) SPIN_UNTIL(&g_wr_ready, NPR);
    __syncthreads();

    float4 al4 = *(const float4*)&alpha[4 * tid];
    float4 rh4 = *(const float4*)&rho[4 * tid];
    float4 ba4 = *(const float4*)&beta_a[4 * tid];
    float al[4] = {al4.x, al4.y, al4.z, al4.w};
    float rh[4] = {rh4.x, rh4.y, rh4.z, rh4.w};
    float ba[4] = {ba4.x, ba4.y, ba4.z, ba4.w};

    float v[4] = {0.f, 0.f, 0.f, 0.f};
    float aa[4] = {0.f, 0.f, 0.f, 0.f};
    float spk[4] = {0.f, 0.f, 0.f, 0.f};
    float v_out = 0.f, osum = 0.f, bo = 0.f;
    if (tid < OO) bo = beta_out[tid];
    int n_act = 0;

    const __half* __restrict__ wr = g_wrecH;

    for (int t = 0; t < TT; ++t) {
        if (tid == 0) SPIN_UNTIL(&g_done[t], NGTILE_N);
        __syncthreads();

        float4 Ic = *(const float4*)&g_Iin[(size_t)(t * BB + b) * HH + 4 * tid];
        float Icur[4] = {Ic.x, Ic.y, Ic.z, Ic.w};

        float Irec[4] = {0.f, 0.f, 0.f, 0.f};
        for (int i = 0; i < n_act; ++i) {
            uint2 w2 = *(const uint2*)(wr + (size_t)act[i] * HH + 4 * tid);
            __half2 p0 = *reinterpret_cast<__half2*>(&w2.x);
            __half2 p1 = *reinterpret_cast<__half2*>(&w2.y);
            Irec[0] += __low2float(p0);
            Irec[1] += __high2float(p0);
            Irec[2] += __low2float(p1);
            Irec[3] += __high2float(p1);
        }

        float spkn[4];
        #pragma unroll
        for (int k = 0; k < 4; ++k) {
            float I1 = Icur[k] + Irec[k];
            float vn = al[k] * v[k] * (1.f - spk[k]) + (1.f - al[k]) * (I1 - aa[k]);
            spkn[k] = (vn > 1.0f) ? 1.f : 0.f;
            aa[k] = rh[k] * aa[k] + (1.f - rh[k]) * (ba[k] * vn + spkn[k]);
            v[k] = vn;
            spk[k] = spkn[k];
        }

        unsigned mybits = (spkn[0] != 0.f ? 1u : 0u) | (spkn[1] != 0.f ? 2u : 0u)
                        | (spkn[2] != 0.f ? 4u : 0u) | (spkn[3] != 0.f ? 8u : 0u);
        int c = __popc(mybits);
        int incl = c;
        #pragma unroll
        for (int dd = 1; dd < 32; dd <<= 1) {
            int y = __shfl_up_sync(0xffffffffu, incl, dd);
            if (lane >= dd) incl += y;
        }
        if (lane == 31) wsum[wid] = incl;
        __syncthreads();
        {
            int woffv = 0, tot = 0;
            #pragma unroll
            for (int w = 0; w < 8; ++w) {
                int s = wsum[w];
                if (w < wid) woffv += s;
                tot += s;
            }
            n_act = tot;
            int p = woffv + incl - c;
            int h0 = 4 * tid;
            if (mybits & 1u) act[p++] = h0;
            if (mybits & 2u) act[p++] = h0 + 1;
            if (mybits & 4u) act[p++] = h0 + 2;
            if (mybits & 8u) act[p++] = h0 + 3;
        }
        __syncthreads();

        if (tid < OO) {
            float accum = 0.f;
            for (int i = 0; i < n_act; ++i)
                accum += g_woutT[(size_t)act[i] * OO + tid];
            v_out = bo * v_out + (1.f - bo) * accum;
            osum += v_out;
        }
    }

    if (tid < OO) out[b * OO + tid] = osum * (1.f / (float)TT);
}

// ---------------------------------------------------------------------------
__global__ __launch_bounds__(256, 2) void mega(
    const float* __restrict__ x, const int* __restrict__ delays,
    const float* __restrict__ w_in, const float* __restrict__ w_rec,
    const float* __restrict__ w_out,
    const float* __restrict__ alpha, const float* __restrict__ rho,
    const float* __restrict__ beta_a, const float* __restrict__ beta_out,
    float* __restrict__ out)
{
    extern __shared__ char smem[];
    const int bid = blockIdx.x;
    if (bid < NPW) {
        prep_w_body(w_in);
    } else if (bid < NPW + NPR) {
        prep_wrec_body(w_rec, w_out, bid - NPW);
    } else if (bid < NPW + NPR + NBLD) {
        build_body(smem, x, delays, bid - (NPW + NPR));
    } else if (bid < NPW + NPR + NBLD + NSNN) {
        snn_body(smem, bid - (NPW + NPR + NBLD), alpha, rho, beta_a, beta_out, out);
    } else {
        gemm_body(smem, bid - (NPW + NPR + NBLD + NSNN));
    }
}

// ---------------------------------------------------------------------------
extern "C" void kernel_launch(void* const* d_in, const int* in_sizes, int n_in,
                              void* d_out, int out_size)
{
    const float* x        = (const float*)d_in[0];
    const int*   delays   = (const int*)  d_in[1];
    const float* w_in     = (const float*)d_in[2];
    const float* w_rec    = (const float*)d_in[3];
    const float* w_out    = (const float*)d_in[4];
    const float* alpha    = (const float*)d_in[5];
    const float* rho      = (const float*)d_in[6];
    const float* beta_a   = (const float*)d_in[7];
    const float* beta_out = (const float*)d_in[8];
    float* out = (float*)d_out;

    static bool attr_set = false;
    if (!attr_set) {
        cudaFuncSetAttribute(mega, cudaFuncAttributeMaxDynamicSharedMemorySize, FUSED_SMEM);
        attr_set = true;
    }

    zero_flags<<<1, 512>>>();
    mega<<<GRID_TOTAL, 256, FUSED_SMEM>>>(x, delays, w_in, w_rec, w_out,
                                          alpha, rho, beta_a, beta_out, out);
}